// round 8
// baseline (speedup 1.0000x reference)
#include <cuda_runtime.h>

// out[r] = W0 + b + sum_c x[r,c] * Y[r,c],
//   Y[r,c] = wlin[c] + sum_{k<=c} Q[k,c] * x[r,k]   (Q upper-triangular)
//
// Register-tiled triangular GEMM. Block: 256 rows x 64 cols, 512 threads.
// Warp w owns 4-column strip sw (k-extent 4*sw+4) x 256 rows, 8 rows/thread.
// Strip permutation balances k-work across SMSPs (each gets exactly 136).
// Per k: 2 LDS.128 (x frag) + 1 LDS.128 (Q broadcast) feed 32 FFMA.

#define DIMS 64
#define BM   256
#define TPB  512
#define NBLK 128
#define XSS  260          // xsT row stride (256 + 4 pad)
#define RSS  17           // reduction stride

#define SMEM_FLOATS (DIMS*XSS + DIMS*DIMS + DIMS + BM*RSS)

__global__ void __launch_bounds__(TPB, 1)
poly_model_kernel(const float* __restrict__ x,
                  const float* __restrict__ W,
                  const float* __restrict__ bias,
                  float* __restrict__ out)
{
    extern __shared__ float sm[];
    float* xsT  = sm;                     // [64][XSS]  x tile, k-major
    float* q    = xsT + DIMS * XSS;       // [64][64]   Q[k][c], zero if k>c
    float* wlin = q + DIMS * DIMS;        // [64]
    float* red  = wlin + DIMS;            // [256][RSS] per-strip partial dots

    const int tid = threadIdx.x;

    // Q[k][c] = W[65 + tri(k,c)] for k<=c, else 0.
    for (int idx = tid; idx < DIMS * DIMS; idx += TPB) {
        const int k = idx >> 6, c = idx & 63;
        float v = 0.0f;
        if (c >= k) {
            const int base = 1 + DIMS + k * DIMS - (k * (k - 1)) / 2;
            v = W[base + (c - k)];
        }
        q[idx] = v;
    }
    if (tid < DIMS) wlin[tid] = W[1 + tid];

    // X tile (256x64) -> transposed smem xsT[k][r], coalesced LDG.128.
    const float4* xg = reinterpret_cast<const float4*>(x)
                     + (size_t)blockIdx.x * BM * (DIMS / 4);
    #pragma unroll
    for (int i = 0; i < BM * (DIMS / 4) / TPB; i++) {   // 8 iters
        const int qi = tid + i * TPB;
        const int r  = qi >> 4;
        const int k4 = qi & 15;
        const float4 v = xg[qi];
        xsT[(4 * k4 + 0) * XSS + r] = v.x;
        xsT[(4 * k4 + 1) * XSS + r] = v.y;
        xsT[(4 * k4 + 2) * XSS + r] = v.z;
        xsT[(4 * k4 + 3) * XSS + r] = v.w;
    }
    __syncthreads();

    const int wid  = tid >> 5;
    const int lane = tid & 31;
    const int g    = wid >> 2;
    const int s    = wid & 3;              // SMSP id
    // Balanced strip permutation: SMSP gets strips summing to 136 k-steps.
    const int sw = (g == 0) ? s : (g == 1) ? 15 - s : (g == 2) ? 4 + s : 11 - s;
    const int cw = sw * 4;                 // first column of strip
    const int Kw = cw + 4;                 // triangle k-extent (warp-uniform)
    const int r0 = lane * 8;               // first of 8 contiguous rows

    // Accumulators init with linear weights (counted once per (r,c)).
    const float4 wl = *reinterpret_cast<const float4*>(&wlin[cw]);
    float acc[8][4];
    #pragma unroll
    for (int rr = 0; rr < 8; rr++) {
        acc[rr][0] = wl.x; acc[rr][1] = wl.y;
        acc[rr][2] = wl.z; acc[rr][3] = wl.w;
    }

    // Triangular k loop: 3 LDS.128 + 32 FFMA per k.
    #pragma unroll 4
    for (int k = 0; k < Kw; k++) {
        const float4 b  = *reinterpret_cast<const float4*>(&q[k * DIMS + cw]);
        const float* xa = &xsT[k * XSS + r0];
        const float4 a0 = *reinterpret_cast<const float4*>(xa);
        const float4 a1 = *reinterpret_cast<const float4*>(xa + 4);
        const float av[8] = {a0.x, a0.y, a0.z, a0.w, a1.x, a1.y, a1.z, a1.w};
        #pragma unroll
        for (int rr = 0; rr < 8; rr++) {
            acc[rr][0] = fmaf(av[rr], b.x, acc[rr][0]);
            acc[rr][1] = fmaf(av[rr], b.y, acc[rr][1]);
            acc[rr][2] = fmaf(av[rr], b.z, acc[rr][2]);
            acc[rr][3] = fmaf(av[rr], b.w, acc[rr][3]);
        }
    }

    // Partial dot over this strip's 4 columns.
    float p[8] = {0, 0, 0, 0, 0, 0, 0, 0};
    #pragma unroll
    for (int c = 0; c < 4; c++) {
        const float* xc = &xsT[(cw + c) * XSS + r0];
        const float4 xa = *reinterpret_cast<const float4*>(xc);
        const float4 xb = *reinterpret_cast<const float4*>(xc + 4);
        p[0] = fmaf(xa.x, acc[0][c], p[0]);
        p[1] = fmaf(xa.y, acc[1][c], p[1]);
        p[2] = fmaf(xa.z, acc[2][c], p[2]);
        p[3] = fmaf(xa.w, acc[3][c], p[3]);
        p[4] = fmaf(xb.x, acc[4][c], p[4]);
        p[5] = fmaf(xb.y, acc[5][c], p[5]);
        p[6] = fmaf(xb.z, acc[6][c], p[6]);
        p[7] = fmaf(xb.w, acc[7][c], p[7]);
    }

    #pragma unroll
    for (int rr = 0; rr < 8; rr++)
        red[(r0 + rr) * RSS + sw] = p[rr];
    __syncthreads();

    // Final cross-strip reduction: one thread per row.
    if (tid < BM) {
        const float* rp = &red[tid * RSS];
        float s0 = 0.f, s1 = 0.f, s2 = 0.f, s3 = 0.f;
        #pragma unroll
        for (int t = 0; t < 16; t += 4) {
            s0 += rp[t + 0]; s1 += rp[t + 1];
            s2 += rp[t + 2]; s3 += rp[t + 3];
        }
        out[blockIdx.x * BM + tid] = (s0 + s1) + (s2 + s3) + W[0] + bias[0];
    }
}

extern "C" void kernel_launch(void* const* d_in, const int* in_sizes, int n_in,
                              void* d_out, int out_size)
{
    const float* x    = (const float*)d_in[0];  // [32768, 64]
    const float* W    = (const float*)d_in[1];  // [2145]
    const float* bias = (const float*)d_in[2];  // [1]
    float* out = (float*)d_out;                 // [32768]

    cudaFuncSetAttribute(poly_model_kernel,
                         cudaFuncAttributeMaxDynamicSharedMemorySize,
                         SMEM_FLOATS * 4);
    poly_model_kernel<<<NBLK, TPB, SMEM_FLOATS * 4>>>(x, W, bias, out);
}

// round 11
// speedup vs baseline: 1.6440x; 1.6440x over previous
#include <cuda_runtime.h>
#include <cuda_bf16.h>
#include <cstdint>

// out[r] = W0 + b + sum_n x[r,n] * ( wlin[n] + D[r,n] ),
//   D[r,n] = sum_k x[r,k] * Q[k,n]   (Q upper-triangular)
// via warp-level bf16 HMMA (mma.sync m16n8k16), split precision:
//   D = Xh*Bh + Xh*Bl + Xl*Bh,  B[n][k] = Q[k][n]
//
// CTA: 256 thr, 256 rows. Warp: 32 rows (2 m16 tiles) x 64 cols (8 n8 tiles).
// Smem tiles stride 144B/row -> conflict-free ldmatrix, no swizzle.
// B in smem is [n][k] (k contiguous) => NON-trans ldmatrix gives the exact
// mma B fragment (b0 = k-pair at (lane&3)*2, n = lane>>2).

#define DIMS 64
#define BM   256
#define TPB  256
#define NBLK 128
#define ASTR 144               // bytes per row (64 bf16 = 128B + 16B pad)

#define SM_WLIN 0              // 64 fp32
#define SM_W0B  256
#define SM_AH   512
#define SM_AL   (SM_AH + BM * ASTR)
#define SM_BH   (SM_AL + BM * ASTR)
#define SM_BL   (SM_BH + DIMS * ASTR)
#define SM_TOTAL (SM_BL + DIMS * ASTR)

__device__ __forceinline__ uint32_t smem_u32(const void* p) {
    uint32_t a;
    asm("{ .reg .u64 t; cvta.to.shared.u64 t, %1; cvt.u32.u64 %0, t; }"
        : "=r"(a) : "l"(p));
    return a;
}

__device__ __forceinline__ void ldsm_x4(uint32_t& a0, uint32_t& a1,
                                        uint32_t& a2, uint32_t& a3, uint32_t addr) {
    asm volatile("ldmatrix.sync.aligned.m8n8.x4.shared.b16 {%0,%1,%2,%3}, [%4];"
                 : "=r"(a0), "=r"(a1), "=r"(a2), "=r"(a3) : "r"(addr));
}
__device__ __forceinline__ void ldsm_x2(uint32_t& b0, uint32_t& b1, uint32_t addr) {
    asm volatile("ldmatrix.sync.aligned.m8n8.x2.shared.b16 {%0,%1}, [%2];"
                 : "=r"(b0), "=r"(b1) : "r"(addr));
}
__device__ __forceinline__ void mma16816(float* c, uint32_t a0, uint32_t a1,
                                         uint32_t a2, uint32_t a3,
                                         uint32_t b0, uint32_t b1) {
    asm volatile(
        "mma.sync.aligned.m16n8k16.row.col.f32.bf16.bf16.f32 "
        "{%0,%1,%2,%3}, {%4,%5,%6,%7}, {%8,%9}, {%0,%1,%2,%3};"
        : "+f"(c[0]), "+f"(c[1]), "+f"(c[2]), "+f"(c[3])
        : "r"(a0), "r"(a1), "r"(a2), "r"(a3), "r"(b0), "r"(b1));
}

__global__ void __launch_bounds__(TPB, 1)
poly_model_kernel(const float* __restrict__ x,
                  const float* __restrict__ W,
                  const float* __restrict__ bias,
                  float* __restrict__ out)
{
    extern __shared__ char smem[];
    const uint32_t sb = smem_u32(smem);
    const int tid  = threadIdx.x;
    const int wid  = tid >> 5;
    const int lane = tid & 31;

    if (tid < DIMS)
        reinterpret_cast<float*>(smem + SM_WLIN)[tid] = W[1 + tid];
    if (tid == 0)
        *reinterpret_cast<float*>(smem + SM_W0B) = W[0] + bias[0];

    // ---- B tiles: B[n][k] = Q[k][n] (k<=n else 0), bf16 hi/lo ----
    #pragma unroll
    for (int it = 0; it < 16; it++) {
        const int idx = tid + it * TPB;          // 0..4095
        const int n = idx >> 6, k = idx & 63;
        float v = 0.0f;
        if (k <= n) {
            const int base = 1 + DIMS + k * DIMS - (k * (k - 1)) / 2;
            v = W[base + (n - k)];
        }
        const __nv_bfloat16 h = __float2bfloat16(v);
        const __nv_bfloat16 l = __float2bfloat16(v - __bfloat162float(h));
        const int off = n * ASTR + k * 2;
        *reinterpret_cast<__nv_bfloat16*>(smem + SM_BH + off) = h;
        *reinterpret_cast<__nv_bfloat16*>(smem + SM_BL + off) = l;
    }

    // ---- A tiles: coalesced fp32 LDG.128, split to bf16 hi/lo ----
    const float4* xg = reinterpret_cast<const float4*>(x)
                     + (size_t)blockIdx.x * BM * (DIMS / 4);
    #pragma unroll
    for (int i = 0; i < 16; i++) {
        const int q    = tid + i * TPB;           // 0..4095
        const float4 v = xg[q];
        const int row  = q >> 4;
        const int c4   = q & 15;                  // float4 index in row

        __nv_bfloat162 h01 = __floats2bfloat162_rn(v.x, v.y);
        __nv_bfloat162 h23 = __floats2bfloat162_rn(v.z, v.w);
        const float2 f01 = __bfloat1622float2(h01);
        const float2 f23 = __bfloat1622float2(h23);
        __nv_bfloat162 l01 = __floats2bfloat162_rn(v.x - f01.x, v.y - f01.y);
        __nv_bfloat162 l23 = __floats2bfloat162_rn(v.z - f23.x, v.w - f23.y);

        const int off = row * ASTR + c4 * 8;
        uint2 hh, ll;
        hh.x = *reinterpret_cast<uint32_t*>(&h01);
        hh.y = *reinterpret_cast<uint32_t*>(&h23);
        ll.x = *reinterpret_cast<uint32_t*>(&l01);
        ll.y = *reinterpret_cast<uint32_t*>(&l23);
        *reinterpret_cast<uint2*>(smem + SM_AH + off) = hh;
        *reinterpret_cast<uint2*>(smem + SM_AL + off) = ll;
    }
    __syncthreads();

    // ---- warp MMA mainloop ----
    float acc[2][8][4];
    #pragma unroll
    for (int m = 0; m < 2; m++)
        #pragma unroll
        for (int n = 0; n < 8; n++)
            #pragma unroll
            for (int t = 0; t < 4; t++) acc[m][n][t] = 0.0f;

    // lane-relative offsets
    // A (x4): lanes 0-7 rows 0-7 klo, 8-15 rows 8-15 klo, 16-23 rows 0-7 khi(+16B), 24-31 rows 8-15 khi
    const uint32_t aLane = (uint32_t)((((lane >> 3) & 1) * 8 + (lane & 7)) * ASTR
                                      + (lane >> 4) * 16);
    // B (x2, non-trans): lanes 0-7 -> n rows 0-7 @ +0 (k0-7), lanes 8-15 -> n rows 0-7 @ +16 (k8-15)
    const uint32_t bLane = (uint32_t)((lane & 7) * ASTR + ((lane >> 3) & 1) * 16);
    const uint32_t aRow0 = (uint32_t)(wid * 32) * ASTR;

    const uint32_t aBase[3] = { sb + SM_AH, sb + SM_AH, sb + SM_AL };
    const uint32_t bBase[3] = { sb + SM_BH, sb + SM_BL, sb + SM_BH };

    #pragma unroll
    for (int pass = 0; pass < 3; pass++) {
        const uint32_t ab = aBase[pass] + aRow0 + aLane;
        const uint32_t bb = bBase[pass] + bLane;
        #pragma unroll
        for (int k = 0; k < 4; k++) {
            const uint32_t kbyte = k * 32;
            uint32_t bf[8][2];
            #pragma unroll
            for (int n = 0; n < 8; n++)
                ldsm_x2(bf[n][0], bf[n][1], bb + n * 8 * ASTR + kbyte);
            #pragma unroll
            for (int m = 0; m < 2; m++) {
                uint32_t a0, a1, a2, a3;
                ldsm_x4(a0, a1, a2, a3, ab + m * 16 * ASTR + kbyte);
                #pragma unroll
                for (int n = 0; n < 8; n++)
                    mma16816(acc[m][n], a0, a1, a2, a3, bf[n][0], bf[n][1]);
            }
        }
    }

    // ---- epilogue: out[r] = sum_c x[c]*(D[c]+wlin[c]) + W0 + b ----
    // D frag: c0/c1 = (row lane>>2, cols n*8+(lane&3)*2, +1), c2/c3 = row+8.
    const float* wlin = reinterpret_cast<const float*>(smem + SM_WLIN);
    const float w0b   = *reinterpret_cast<const float*>(smem + SM_W0B);

    #pragma unroll
    for (int m = 0; m < 2; m++) {
        const int r0 = wid * 32 + m * 16 + (lane >> 2);   // local row
        const int r1 = r0 + 8;
        float p0 = 0.0f, p1 = 0.0f;
        #pragma unroll
        for (int n = 0; n < 8; n++) {
            const int c0 = n * 8 + (lane & 3) * 2;
            const float2 wl = *reinterpret_cast<const float2*>(&wlin[c0]);

            const int o0 = r0 * ASTR + c0 * 2;
            const int o1 = r1 * ASTR + c0 * 2;
            const float2 xh0 = __bfloat1622float2(
                *reinterpret_cast<const __nv_bfloat162*>(smem + SM_AH + o0));
            const float2 xl0 = __bfloat1622float2(
                *reinterpret_cast<const __nv_bfloat162*>(smem + SM_AL + o0));
            const float2 xh1 = __bfloat1622float2(
                *reinterpret_cast<const __nv_bfloat162*>(smem + SM_AH + o1));
            const float2 xl1 = __bfloat1622float2(
                *reinterpret_cast<const __nv_bfloat162*>(smem + SM_AL + o1));

            p0 = fmaf(xh0.x + xl0.x, acc[m][n][0] + wl.x, p0);
            p0 = fmaf(xh0.y + xl0.y, acc[m][n][1] + wl.y, p0);
            p1 = fmaf(xh1.x + xl1.x, acc[m][n][2] + wl.x, p1);
            p1 = fmaf(xh1.y + xl1.y, acc[m][n][3] + wl.y, p1);
        }
        // reduce across the 4 lanes sharing each row
        p0 += __shfl_xor_sync(0xffffffffu, p0, 1);
        p0 += __shfl_xor_sync(0xffffffffu, p0, 2);
        p1 += __shfl_xor_sync(0xffffffffu, p1, 1);
        p1 += __shfl_xor_sync(0xffffffffu, p1, 2);
        if ((lane & 3) == 0) {
            const int gr = blockIdx.x * BM;
            out[gr + r0] = p0 + w0b;
            out[gr + r1] = p1 + w0b;
        }
    }
}

extern "C" void kernel_launch(void* const* d_in, const int* in_sizes, int n_in,
                              void* d_out, int out_size)
{
    const float* x    = (const float*)d_in[0];  // [32768, 64]
    const float* W    = (const float*)d_in[1];  // [2145]
    const float* bias = (const float*)d_in[2];  // [1]
    float* out = (float*)d_out;                 // [32768]

    cudaFuncSetAttribute(poly_model_kernel,
                         cudaFuncAttributeMaxDynamicSharedMemorySize, SM_TOTAL);
    poly_model_kernel<<<NBLK, TPB, SM_TOTAL>>>(x, W, bias, out);
}